// round 13
// baseline (speedup 1.0000x reference)
#include <cuda_runtime.h>

// Haar level-1 high-pass: out = x - mean(2x2 block), x shape (8, 64, 512, 512) fp32.
// Flattened view: rows of length W=512, total rows R = 8*64*512 = 262144.
// Each thread: one row-pair (2r, 2r+1) x 4 columns => two float4 loads, two float4 stores.
//
// FINAL (measured optimum, reproduced 7x on hardware): 148.4-149.8us kernel,
// 6.82-6.87 TB/s, 86-87% DRAM-active — the B300 mixed read/write streaming
// ceiling. Bench-level spread of this exact source: 155.7-157.3us (pure noise).
// Measured and rejected:
//   - v8.f32 256-bit ld/st:      neutral (LSU/wavefront path never the limiter)
//   - __ldcs/__stcs streaming:   neutral (touch-once already streams)
//   - TPB=512:                   neutral
//   - persistent grid-stride:    -12% (serializes per-thread MLP; flat
//                                short-lived warps maximize in-flight loads)
//   - 4-load front-batched tile: neutral
// Traffic is provably minimal: 512 MiB read + 512 MiB write, zero reuse,
// fp32 output mandated. HBM-bound at the roofline; the residual ~13% is DRAM
// read/write bus turnaround, not addressable from SASS.

static constexpr int W      = 512;
static constexpr int W4     = W / 4;           // 128 float4 per row
static constexpr int ROWS   = 8 * 64 * 512;    // 262144 rows
static constexpr int NUNITS = (ROWS / 2) * W4; // 16,777,216 thread-units

__global__ void __launch_bounds__(256) fastwt_high_kernel(
    const float4* __restrict__ in, float4* __restrict__ out)
{
    int idx = blockIdx.x * blockDim.x + threadIdx.x;   // < NUNITS (exact grid)
    int cw      = idx & (W4 - 1);     // column group 0..127
    int rowpair = idx >> 7;           // idx / 128

    int i0 = rowpair * (2 * W4) + cw; // float4 index, row 2r
    int i1 = i0 + W4;                 // row 2r+1

    float4 a = in[i0];
    float4 b = in[i1];

    float m0 = (a.x + a.y + b.x + b.y) * 0.25f;
    float m1 = (a.z + a.w + b.z + b.w) * 0.25f;

    float4 o0 = make_float4(a.x - m0, a.y - m0, a.z - m1, a.w - m1);
    float4 o1 = make_float4(b.x - m0, b.y - m0, b.z - m1, b.w - m1);

    out[i0] = o0;
    out[i1] = o1;
}

extern "C" void kernel_launch(void* const* d_in, const int* in_sizes, int n_in,
                              void* d_out, int out_size)
{
    const float4* in  = (const float4*)d_in[0];
    float4*       out = (float4*)d_out;
    constexpr int TPB = 256;
    fastwt_high_kernel<<<NUNITS / TPB, TPB>>>(in, out);
}

// round 14
// speedup vs baseline: 1.0018x; 1.0018x over previous
#include <cuda_runtime.h>

// Haar level-1 high-pass: out = x - mean(2x2 block), x shape (8, 64, 512, 512) fp32.
// Flattened view: rows of length W=512, total rows R = 8*64*512 = 262144.
// Each thread: one row-pair (2r, 2r+1) x 4 columns => two float4 loads, two float4 stores.
//
// Same 2-load flat formulation as the measured optimum (148.4-150.3us kernel,
// 86-87% DRAM over 8 runs). Last unmeasured cell: TPB=128 (256 and 512 tested
// neutral). Finer CTA granularity -> smaller last-wave drain quantum; bounded
// small at DRAM saturation, revert to TPB=256 if not a repeatable win.

static constexpr int W      = 512;
static constexpr int W4     = W / 4;           // 128 float4 per row
static constexpr int ROWS   = 8 * 64 * 512;    // 262144 rows
static constexpr int NUNITS = (ROWS / 2) * W4; // 16,777,216 thread-units

__global__ void __launch_bounds__(128) fastwt_high_kernel(
    const float4* __restrict__ in, float4* __restrict__ out)
{
    int idx = blockIdx.x * blockDim.x + threadIdx.x;   // < NUNITS (exact grid)
    int cw      = idx & (W4 - 1);     // column group 0..127
    int rowpair = idx >> 7;           // idx / 128

    int i0 = rowpair * (2 * W4) + cw; // float4 index, row 2r
    int i1 = i0 + W4;                 // row 2r+1

    float4 a = in[i0];
    float4 b = in[i1];

    float m0 = (a.x + a.y + b.x + b.y) * 0.25f;
    float m1 = (a.z + a.w + b.z + b.w) * 0.25f;

    float4 o0 = make_float4(a.x - m0, a.y - m0, a.z - m1, a.w - m1);
    float4 o1 = make_float4(b.x - m0, b.y - m0, b.z - m1, b.w - m1);

    out[i0] = o0;
    out[i1] = o1;
}

extern "C" void kernel_launch(void* const* d_in, const int* in_sizes, int n_in,
                              void* d_out, int out_size)
{
    const float4* in  = (const float4*)d_in[0];
    float4*       out = (float4*)d_out;
    constexpr int TPB = 128;
    fastwt_high_kernel<<<NUNITS / TPB, TPB>>>(in, out);
}

// round 15
// speedup vs baseline: 1.0045x; 1.0027x over previous
#include <cuda_runtime.h>

// Haar level-1 high-pass: out = x - mean(2x2 block), x shape (8, 64, 512, 512) fp32.
// Flattened view: rows of length W=512, total rows R = 8*64*512 = 262144.
// Each thread: one row-pair (2r, 2r+1) x 4 columns => two float4 loads, two float4 stores.
//
// FINAL (measured optimum, 9 hardware rounds): 148.4-150.3us kernel,
// 6.78-6.87 TB/s, 85-87% DRAM-active — the B300 mixed read/write streaming
// ceiling. Bench spread of this source: 155.7-157.3us (noise).
// Full lever matrix, all measured:
//   - vector width 16B vs 32B (v8.f32):  neutral
//   - cache policy (__ldcs/__stcs):      neutral
//   - TPB 128 / 256 / 512:               neutral
//   - persistent grid-stride:            -12% (serializes per-thread MLP)
//   - 4-load front-batched tile:         neutral
// Traffic provably minimal: 512 MiB read + 512 MiB write, zero reuse, fp32
// output mandated. Residual ~14% to spec is DRAM read/write bus turnaround,
// not addressable from SASS. HBM-bound at the roofline.

static constexpr int W      = 512;
static constexpr int W4     = W / 4;           // 128 float4 per row
static constexpr int ROWS   = 8 * 64 * 512;    // 262144 rows
static constexpr int NUNITS = (ROWS / 2) * W4; // 16,777,216 thread-units

__global__ void __launch_bounds__(256) fastwt_high_kernel(
    const float4* __restrict__ in, float4* __restrict__ out)
{
    int idx = blockIdx.x * blockDim.x + threadIdx.x;   // < NUNITS (exact grid)
    int cw      = idx & (W4 - 1);     // column group 0..127
    int rowpair = idx >> 7;           // idx / 128

    int i0 = rowpair * (2 * W4) + cw; // float4 index, row 2r
    int i1 = i0 + W4;                 // row 2r+1

    float4 a = in[i0];
    float4 b = in[i1];

    float m0 = (a.x + a.y + b.x + b.y) * 0.25f;
    float m1 = (a.z + a.w + b.z + b.w) * 0.25f;

    float4 o0 = make_float4(a.x - m0, a.y - m0, a.z - m1, a.w - m1);
    float4 o1 = make_float4(b.x - m0, b.y - m0, b.z - m1, b.w - m1);

    out[i0] = o0;
    out[i1] = o1;
}

extern "C" void kernel_launch(void* const* d_in, const int* in_sizes, int n_in,
                              void* d_out, int out_size)
{
    const float4* in  = (const float4*)d_in[0];
    float4*       out = (float4*)d_out;
    constexpr int TPB = 256;
    fastwt_high_kernel<<<NUNITS / TPB, TPB>>>(in, out);
}

// round 16
// speedup vs baseline: 1.0064x; 1.0018x over previous
#include <cuda_runtime.h>

// Haar level-1 high-pass: out = x - mean(2x2 block), x shape (8, 64, 512, 512) fp32.
// Flattened view: rows of length W=512, total rows R = 8*64*512 = 262144.
// Each thread: one row-pair (2r, 2r+1) x 4 columns => two float4 loads, two float4 stores.
//
// FINAL (measured optimum, 10 hardware rounds): 148.4-150.3us kernel,
// 6.78-6.87 TB/s, 85-87% DRAM-active — the B300 mixed read/write streaming
// ceiling. Bench spread of this source: 155.7-157.3us (noise).
// Full lever matrix, all measured:
//   - vector width 16B vs 32B (v8.f32):  neutral
//   - cache policy (__ldcs/__stcs):      neutral
//   - TPB 128 / 256 / 512:               neutral
//   - persistent grid-stride:            -12% (serializes per-thread MLP)
//   - 4-load front-batched tile:         neutral
// Traffic provably minimal: 512 MiB read + 512 MiB write, zero reuse, fp32
// output mandated. Residual ~14% to spec is DRAM read/write bus turnaround,
// not addressable from SASS. HBM-bound at the roofline.

static constexpr int W      = 512;
static constexpr int W4     = W / 4;           // 128 float4 per row
static constexpr int ROWS   = 8 * 64 * 512;    // 262144 rows
static constexpr int NUNITS = (ROWS / 2) * W4; // 16,777,216 thread-units

__global__ void __launch_bounds__(256) fastwt_high_kernel(
    const float4* __restrict__ in, float4* __restrict__ out)
{
    int idx = blockIdx.x * blockDim.x + threadIdx.x;   // < NUNITS (exact grid)
    int cw      = idx & (W4 - 1);     // column group 0..127
    int rowpair = idx >> 7;           // idx / 128

    int i0 = rowpair * (2 * W4) + cw; // float4 index, row 2r
    int i1 = i0 + W4;                 // row 2r+1

    float4 a = in[i0];
    float4 b = in[i1];

    float m0 = (a.x + a.y + b.x + b.y) * 0.25f;
    float m1 = (a.z + a.w + b.z + b.w) * 0.25f;

    float4 o0 = make_float4(a.x - m0, a.y - m0, a.z - m1, a.w - m1);
    float4 o1 = make_float4(b.x - m0, b.y - m0, b.z - m1, b.w - m1);

    out[i0] = o0;
    out[i1] = o1;
}

extern "C" void kernel_launch(void* const* d_in, const int* in_sizes, int n_in,
                              void* d_out, int out_size)
{
    const float4* in  = (const float4*)d_in[0];
    float4*       out = (float4*)d_out;
    constexpr int TPB = 256;
    fastwt_high_kernel<<<NUNITS / TPB, TPB>>>(in, out);
}